// round 1
// baseline (speedup 1.0000x reference)
#include <cuda_runtime.h>
#include <math.h>

#define NB   128   // CTAs (<= SM count, guaranteed co-resident)
#define TPB  256
#define Bsz  128
#define Tsz  512
#define ISZ  128
#define Hsz  1024
#define ACC_STRIDE 4096

// ---------------- persistent state (zero-init; every launch resets what it uses) ----
__device__ float g_h1[Bsz*Hsz];
__device__ float g_c1[Bsz*Hsz];
__device__ float g_h2[Bsz*Hsz];
__device__ float g_c2[Bsz*Hsz];
__device__ float g_x [Bsz*ISZ];
__device__ float g_x2[Bsz*Hsz];
__device__ float g_hm[Bsz*Hsz];
__device__ float g_acc[Bsz*ACC_STRIDE];   // partial-sum accumulator, kept zeroed by finishers
__device__ int   g_cnt[128];              // per n-tile completion counters (reset by finisher)
__device__ unsigned g_barcnt;
__device__ volatile unsigned g_bargen;

// ---------------- grid barrier (sense via generation counter) ----------------------
__device__ __forceinline__ void gridbar() {
    __syncthreads();
    if (threadIdx.x == 0) {
        __threadfence();
        unsigned gen = g_bargen;
        if (atomicAdd(&g_barcnt, 1u) == (unsigned)(gridDim.x - 1)) {
            g_barcnt = 0;
            __threadfence();
            atomicExch((unsigned*)&g_bargen, gen + 1u);
        } else {
            while (g_bargen == gen) { __nanosleep(64); }
        }
        __threadfence();
    }
    __syncthreads();
}

// ---------------- phase descriptor ------------------------------------------------
struct Cfg {
    const float* A1; const float* A2; int K1;   // A(b,k): k<K1 -> A1[b*K1+k] else A2[b*H+(k-K1)]
    const float* W1; const float* W2; int KW1;  // mog: W1[n*KW1+k]; lstm: row=g*H+u split Wih/Whh
    int N, K, KCH, lstm;
    const float* b1; const float* b2;           // mog: b1; lstm: bih,bhh
    const float* mult; int mstride;             // mog epilogue multiplicand
    float* out; int ostride;                    // mog output
    float* fc; float* fh;                       // lstm state
};

// one GEMM phase: split over (n-tile of 32 cols) x (KCH k-chunks); partial sums
// atomicAdd into g_acc; the LAST CTA of each n-tile runs the fused epilogue.
__device__ __noinline__ void run_phase(Cfg c) {
    __shared__ float As[32*132];   // [k][b], padded stride
    __shared__ float Ws[32*36];    // [k][n], padded stride
    __shared__ int   s_last;
    int cta = blockIdx.x;
    int ntiles = c.N >> 5;
    int total = ntiles * c.KCH;
    if (cta < total) {
        int tile = cta / c.KCH;
        int kc   = cta - tile * c.KCH;
        int n0   = tile << 5;
        int KL   = c.K / c.KCH;
        int k0   = kc * KL;
        int tid  = threadIdx.x;
        int tm = tid & 31, tn = tid >> 5;   // thread tile: 4 rows x 4 cols
        float acc[4][4];
        #pragma unroll
        for (int i = 0; i < 4; i++)
            #pragma unroll
            for (int j = 0; j < 4; j++) acc[i][j] = 0.f;

        for (int kb = 0; kb < KL; kb += 32) {
            int kbase = k0 + kb;
            // stage A tile (transposed) — coalesced reads along k
            for (int idx = tid; idx < Bsz*32; idx += TPB) {
                int b = idx >> 5, kk = idx & 31;
                int k = kbase + kk;
                float v = (k < c.K1) ? c.A1[b*c.K1 + k] : c.A2[b*Hsz + (k - c.K1)];
                As[kk*132 + b] = v;
            }
            // stage W tile
            for (int idx = tid; idx < 32*32; idx += TPB) {
                int n = idx >> 5, kk = idx & 31;
                int k = kbase + kk;
                int nn = n0 + n;
                float v;
                if (c.lstm) {
                    int g = nn & 3, u = nn >> 2;
                    int row = g*Hsz + u;
                    v = (k < c.K1) ? c.W1[row*c.KW1 + k] : c.W2[row*Hsz + (k - c.K1)];
                } else {
                    v = c.W1[nn*c.KW1 + k];
                }
                Ws[kk*36 + n] = v;
            }
            __syncthreads();
            #pragma unroll
            for (int kk = 0; kk < 32; ++kk) {
                float4 a = *(const float4*)(As + kk*132 + (tm << 2));
                float4 w = *(const float4*)(Ws + kk*36  + (tn << 2));
                acc[0][0] += a.x*w.x; acc[0][1] += a.x*w.y; acc[0][2] += a.x*w.z; acc[0][3] += a.x*w.w;
                acc[1][0] += a.y*w.x; acc[1][1] += a.y*w.y; acc[1][2] += a.y*w.z; acc[1][3] += a.y*w.w;
                acc[2][0] += a.z*w.x; acc[2][1] += a.z*w.y; acc[2][2] += a.z*w.z; acc[2][3] += a.z*w.w;
                acc[3][0] += a.w*w.x; acc[3][1] += a.w*w.y; acc[3][2] += a.w*w.z; acc[3][3] += a.w*w.w;
            }
            __syncthreads();
        }
        // accumulate partials
        #pragma unroll
        for (int i = 0; i < 4; i++)
            #pragma unroll
            for (int j = 0; j < 4; j++)
                atomicAdd(&g_acc[(tm*4 + i)*ACC_STRIDE + n0 + tn*4 + j], acc[i][j]);
        __threadfence();
        if (tid == 0) s_last = (atomicAdd(&g_cnt[tile], 1) == c.KCH - 1) ? 1 : 0;
        __syncthreads();
        if (s_last) {
            __threadfence();
            if (tid == 0) g_cnt[tile] = 0;
            if (!c.lstm) {
                for (int idx = tid; idx < Bsz*32; idx += TPB) {
                    int b = idx >> 5, n = n0 + (idx & 31);
                    float* ap = &g_acc[b*ACC_STRIDE + n];
                    float z = *ap + c.b1[n];
                    *ap = 0.f;
                    float s = 2.f / (1.f + expf(-z));
                    c.out[b*c.ostride + n] = s * c.mult[b*c.mstride + n];
                }
            } else {
                int u0 = n0 >> 2;
                for (int idx = tid; idx < Bsz*8; idx += TPB) {
                    int b = idx >> 3, u = u0 + (idx & 7);
                    float* ap = &g_acc[b*ACC_STRIDE + u*4];
                    float zi = ap[0] + c.b1[0*Hsz+u] + c.b2[0*Hsz+u];
                    float zf = ap[1] + c.b1[1*Hsz+u] + c.b2[1*Hsz+u];
                    float zg = ap[2] + c.b1[2*Hsz+u] + c.b2[2*Hsz+u];
                    float zo = ap[3] + c.b1[3*Hsz+u] + c.b2[3*Hsz+u];
                    ap[0] = 0.f; ap[1] = 0.f; ap[2] = 0.f; ap[3] = 0.f;
                    float si = 1.f/(1.f+expf(-zi));
                    float sf = 1.f/(1.f+expf(-zf));
                    float so = 1.f/(1.f+expf(-zo));
                    float cn = sf * c.fc[b*Hsz+u] + si * tanhf(zg);
                    float hn = so * tanhf(cn);
                    c.fc[b*Hsz+u] = cn;
                    c.fh[b*Hsz+u] = hn;
                }
            }
        }
    }
    gridbar();
}

__device__ __forceinline__ Cfg mog_cfg(const float* A, int K, const float* W, int KW,
                                       int N, int KCH, const float* bias,
                                       const float* mult, int mstride,
                                       float* out, int ostride) {
    Cfg c;
    c.A1 = A; c.A2 = A; c.K1 = K;
    c.W1 = W; c.W2 = W; c.KW1 = KW;
    c.N = N; c.K = K; c.KCH = KCH; c.lstm = 0;
    c.b1 = bias; c.b2 = bias;
    c.mult = mult; c.mstride = mstride;
    c.out = out; c.ostride = ostride;
    c.fc = 0; c.fh = 0;
    return c;
}

__global__ void __launch_bounds__(TPB) mog_kernel(
    const float* in_seq,
    const float* c1Q, const float* c1Qb, const float* c1R, const float* c1Rb,
    const float* c1Wih, const float* c1Whh, const float* c1bih, const float* c1bhh,
    const float* c2Q, const float* c2Qb, const float* c2R, const float* c2Rb,
    const float* c2Wih, const float* c2Whh, const float* c2bih, const float* c2bhh,
    const float* linW, const float* linb, float* out)
{
    // zero states
    for (int i = blockIdx.x*TPB + threadIdx.x; i < Bsz*Hsz; i += NB*TPB) {
        g_h1[i] = 0.f; g_c1[i] = 0.f; g_h2[i] = 0.f; g_c2[i] = 0.f;
    }
    gridbar();

    for (int t = 0; t < Tsz; ++t) {
        // ---- layer 1 mogrify ----
        run_phase(mog_cfg(g_h1, Hsz, c1Q,              Hsz, ISZ, 32, c1Qb,
                          in_seq + t*ISZ, Tsz*ISZ, g_x, ISZ));                     // x = 2s(h1 Q0^T)*x_t
        run_phase(mog_cfg(g_x,  ISZ, c1R,              ISZ, Hsz,  4, c1Rb,
                          g_h1, Hsz, g_hm, Hsz));                                  // hm = 2s(x R0^T)*h1
        run_phase(mog_cfg(g_hm, Hsz, c1Q + ISZ*Hsz,    Hsz, ISZ, 32, c1Qb + ISZ,
                          g_x, ISZ, g_x, ISZ));                                    // x *= 2s(hm Q1^T)
        run_phase(mog_cfg(g_x,  ISZ, c1R + Hsz*ISZ,    ISZ, Hsz,  4, c1Rb + Hsz,
                          g_hm, Hsz, g_hm, Hsz));                                  // hm *= 2s(x R1^T)
        run_phase(mog_cfg(g_hm, Hsz, c1Q + 2*ISZ*Hsz,  Hsz, ISZ, 32, c1Qb + 2*ISZ,
                          g_x, ISZ, g_x, ISZ));                                    // x *= 2s(hm Q2^T)
        // ---- layer 1 LSTM ----
        {
            Cfg c;
            c.A1 = g_x; c.A2 = g_hm; c.K1 = ISZ;
            c.W1 = c1Wih; c.W2 = c1Whh; c.KW1 = ISZ;
            c.N = 4096; c.K = ISZ + Hsz; c.KCH = 1; c.lstm = 1;
            c.b1 = c1bih; c.b2 = c1bhh;
            c.mult = 0; c.mstride = 0; c.out = 0; c.ostride = 0;
            c.fc = g_c1; c.fh = g_h1;
            run_phase(c);
        }
        // ---- layer 2 mogrify (x starts as h1, h is h2) ----
        run_phase(mog_cfg(g_h2, Hsz, c2Q,             Hsz, Hsz, 4, c2Qb,
                          g_h1, Hsz, g_x2, Hsz));                                  // x2 = 2s(h2 Q0^T)*h1
        run_phase(mog_cfg(g_x2, Hsz, c2R,             Hsz, Hsz, 4, c2Rb,
                          g_h2, Hsz, g_hm, Hsz));                                  // hm = 2s(x2 R0^T)*h2
        run_phase(mog_cfg(g_hm, Hsz, c2Q + Hsz*Hsz,   Hsz, Hsz, 4, c2Qb + Hsz,
                          g_x2, Hsz, g_x2, Hsz));                                  // x2 *= 2s(hm Q1^T)
        run_phase(mog_cfg(g_x2, Hsz, c2R + Hsz*Hsz,   Hsz, Hsz, 4, c2Rb + Hsz,
                          g_hm, Hsz, g_hm, Hsz));                                  // hm *= 2s(x2 R1^T)
        run_phase(mog_cfg(g_hm, Hsz, c2Q + 2*Hsz*Hsz, Hsz, Hsz, 4, c2Qb + 2*Hsz,
                          g_x2, Hsz, g_x2, Hsz));                                  // x2 *= 2s(hm Q2^T)
        // ---- layer 2 LSTM ----
        {
            Cfg c;
            c.A1 = g_x2; c.A2 = g_hm; c.K1 = Hsz;
            c.W1 = c2Wih; c.W2 = c2Whh; c.KW1 = Hsz;
            c.N = 4096; c.K = 2*Hsz; c.KCH = 1; c.lstm = 1;
            c.b1 = c2bih; c.b2 = c2bhh;
            c.mult = 0; c.mstride = 0; c.out = 0; c.ostride = 0;
            c.fc = g_c2; c.fh = g_h2;
            run_phase(c);
        }
    }

    // final linear: out[b] = h2[b,:] . linW + linb  (only last step needed)
    if (blockIdx.x == 0) {
        int tid = threadIdx.x;
        int b = tid >> 1, half = tid & 1;
        const float* hrow = g_h2 + b*Hsz + half*512;
        const float* w    = linW + half*512;
        float s = 0.f;
        for (int j = 0; j < 512; ++j) s += hrow[j] * w[j];
        s += __shfl_xor_sync(0xffffffffu, s, 1);
        if (half == 0) out[b] = s + linb[0];
    }
}

extern "C" void kernel_launch(void* const* d_in, const int* in_sizes, int n_in,
                              void* d_out, int out_size) {
    (void)in_sizes; (void)n_in; (void)out_size;
    const float* in_seq = (const float*)d_in[0];
    const float* c1Q    = (const float*)d_in[1];
    const float* c1Qb   = (const float*)d_in[2];
    const float* c1R    = (const float*)d_in[3];
    const float* c1Rb   = (const float*)d_in[4];
    const float* c1Wih  = (const float*)d_in[5];
    const float* c1Whh  = (const float*)d_in[6];
    const float* c1bih  = (const float*)d_in[7];
    const float* c1bhh  = (const float*)d_in[8];
    const float* c2Q    = (const float*)d_in[9];
    const float* c2Qb   = (const float*)d_in[10];
    const float* c2R    = (const float*)d_in[11];
    const float* c2Rb   = (const float*)d_in[12];
    const float* c2Wih  = (const float*)d_in[13];
    const float* c2Whh  = (const float*)d_in[14];
    const float* c2bih  = (const float*)d_in[15];
    const float* c2bhh  = (const float*)d_in[16];
    const float* linW   = (const float*)d_in[17];
    const float* linb   = (const float*)d_in[18];
    mog_kernel<<<NB, TPB>>>(in_seq, c1Q, c1Qb, c1R, c1Rb, c1Wih, c1Whh, c1bih, c1bhh,
                            c2Q, c2Qb, c2R, c2Rb, c2Wih, c2Whh, c2bih, c2bhh,
                            linW, linb, (float*)d_out);
}

// round 2
// speedup vs baseline: 1.0539x; 1.0539x over previous
#include <cuda_runtime.h>
#include <mma.h>
#include <math.h>

using namespace nvcuda;

#define NB   128
#define TPB  256
#define Bsz  128
#define Tsz  512
#define ISZ  128
#define Hsz  1024

// ---------------- persistent state --------------------------------------------
__device__ float g_h1[Bsz*Hsz];
__device__ float g_c1[Bsz*Hsz];
__device__ float g_h2[Bsz*Hsz];
__device__ float g_c2[Bsz*Hsz];
__device__ float g_x [Bsz*ISZ];
__device__ float g_x2[Bsz*Hsz];
__device__ float g_hm[Bsz*Hsz];
__device__ float g_acc[Bsz*ISZ];     // split-K accumulator (only layer-1 Q phases)
__device__ int   g_cnt[32];
__device__ unsigned g_barcnt;
__device__ volatile unsigned g_bargen;

// ---------------- grid barrier ------------------------------------------------
__device__ __forceinline__ void gridbar() {
    __syncthreads();
    if (threadIdx.x == 0) {
        __threadfence();
        unsigned gen = g_bargen;
        if (atomicAdd(&g_barcnt, 1u) == (unsigned)(gridDim.x - 1)) {
            g_barcnt = 0;
            __threadfence();
            atomicExch((unsigned*)&g_bargen, gen + 1u);
        } else {
            while (g_bargen == gen) { __nanosleep(64); }
        }
        __threadfence();
    }
    __syncthreads();
}

// ---------------- phase descriptor --------------------------------------------
struct P {
    const float *A1, *A2; int K1, Ktot;   // A(b,k): k<K1 -> A1[b*K1+k] else A2[b*Hsz+k-K1]
    const float *W1, *W2; int KW1;        // weight matrices (row-major [row][k])
    int lstm;                             // lstm: n=u*4+g -> row=g*Hsz+u, split W1/W2 at K1
    int N, nshift, kch;                   // nstrip = 1<<nshift
    const float *b1, *b2;
    const float *mult; int mstride;       // mog epilogue multiplicand
    float *out; int ostride;              // mog output
    float *fc, *fh;                       // lstm state
};

__device__ __forceinline__ float sigm(float z) { return 1.f / (1.f + expf(-z)); }

// one GEMM phase, wmma tf32 with 3xTF32 compensation
__device__ __noinline__ void run_phase(const P p) {
    __shared__ float sm[4096];            // staging (AH|AL|WH|WL) and output tile
    __shared__ int   s_last;
    float* AH = sm;
    float* AL = sm + 1024;
    float* WH = sm + 2048;
    float* WL = sm + 3072;

    const int tid = threadIdx.x;
    const int wid = tid >> 5;
    const int nstrip = 1 << p.nshift;
    const int ntiles = p.N >> p.nshift;
    const int total  = 2 * ntiles * p.kch;
    const int cta = blockIdx.x;

    if (cta < total) {
        const int tile = cta / p.kch, kc = cta - tile * p.kch;
        const int mt = tile / ntiles,  nt = tile - mt * ntiles;
        const int m0 = mt << 6;
        const int n0 = nt << p.nshift;
        const int KL = p.Ktot / p.kch;
        const int k0 = kc * KL;
        const int nW = nstrip >> 2;       // 4 * nstrip/16 warp-tiles in CTA

        wmma::fragment<wmma::accumulator, 16, 16, 8, float> C[2];
        wmma::fill_fragment(C[0], 0.f);
        wmma::fill_fragment(C[1], 0.f);
        const int tm = wid & 3;

        const int am = tid >> 2, akq = (tid & 3) << 2;    // A stage: (m, k-quad)
        const int wnn = tid >> 2, wkq = (tid & 3) << 2;   // W stage: (n, k-quad)

        for (int kb = 0; kb < KL; kb += 16) {
            const int kg = k0 + kb;
            // ---- stage A (64 x 16, hi/lo) ----
            {
                int b = m0 + am;
                int k = kg + akq;
                const float* src = (k < p.K1) ? (p.A1 + b * p.K1 + k)
                                              : (p.A2 + b * Hsz + (k - p.K1));
                float4 v = __ldcg((const float4*)src);
                float h0 = wmma::__float_to_tf32(v.x);
                float h1 = wmma::__float_to_tf32(v.y);
                float h2 = wmma::__float_to_tf32(v.z);
                float h3 = wmma::__float_to_tf32(v.w);
                int o = am * 16 + akq;
                AH[o+0]=h0; AH[o+1]=h1; AH[o+2]=h2; AH[o+3]=h3;
                AL[o+0]=wmma::__float_to_tf32(v.x-h0);
                AL[o+1]=wmma::__float_to_tf32(v.y-h1);
                AL[o+2]=wmma::__float_to_tf32(v.z-h2);
                AL[o+3]=wmma::__float_to_tf32(v.w-h3);
            }
            // ---- stage W^T (16 x nstrip, hi/lo) ----
            if (tid < (nstrip << 2)) {
                int n = n0 + wnn;
                int k = kg + wkq;
                int row;
                if (p.lstm) { int g = n & 3, u = n >> 2; row = g * Hsz + u; }
                else        row = n;
                float4 v = (k < p.K1) ? *(const float4*)(p.W1 + row * p.KW1 + k)
                                      : *(const float4*)(p.W2 + row * Hsz + (k - p.K1));
                float h0 = wmma::__float_to_tf32(v.x);
                float h1 = wmma::__float_to_tf32(v.y);
                float h2 = wmma::__float_to_tf32(v.z);
                float h3 = wmma::__float_to_tf32(v.w);
                int o = wkq * nstrip + wnn;
                WH[o]            = h0;  WL[o]            = wmma::__float_to_tf32(v.x-h0);
                WH[o+  nstrip]   = h1;  WL[o+  nstrip]   = wmma::__float_to_tf32(v.y-h1);
                WH[o+2*nstrip]   = h2;  WL[o+2*nstrip]   = wmma::__float_to_tf32(v.z-h2);
                WH[o+3*nstrip]   = h3;  WL[o+3*nstrip]   = wmma::__float_to_tf32(v.w-h3);
            }
            __syncthreads();
            // ---- compute ----
            if (wid < nW) {
                wmma::fragment<wmma::matrix_a, 16,16,8, wmma::precision::tf32, wmma::row_major> aH, aL;
                wmma::fragment<wmma::matrix_b, 16,16,8, wmma::precision::tf32, wmma::row_major> bH, bL;
                #pragma unroll
                for (int ks = 0; ks < 2; ++ks) {
                    wmma::load_matrix_sync(aH, AH + tm*16*16 + ks*8, 16);
                    wmma::load_matrix_sync(aL, AL + tm*16*16 + ks*8, 16);
                    #pragma unroll
                    for (int r = 0; r < 2; ++r) {
                        int wt = wid + (r << 3);
                        if (wt < nW) {
                            int tn = wt >> 2;
                            wmma::load_matrix_sync(bH, WH + ks*8*nstrip + tn*16, nstrip);
                            wmma::load_matrix_sync(bL, WL + ks*8*nstrip + tn*16, nstrip);
                            wmma::mma_sync(C[r], aH, bH, C[r]);
                            wmma::mma_sync(C[r], aH, bL, C[r]);
                            wmma::mma_sync(C[r], aL, bH, C[r]);
                        }
                    }
                }
            }
            __syncthreads();
        }

        // ---- dump accumulators to smem tile (64 x nstrip, row-major ld=nstrip) ----
        if (wid < nW) {
            #pragma unroll
            for (int r = 0; r < 2; ++r) {
                int wt = wid + (r << 3);
                if (wt < nW) {
                    int tn = wt >> 2;
                    wmma::store_matrix_sync(sm + tm*16*nstrip + tn*16, C[r], nstrip,
                                            wmma::mem_row_major);
                }
            }
        }
        __syncthreads();

        if (p.kch == 1) {
            if (!p.lstm) {
                const int tot = nstrip << 6;
                for (int e = tid; e < tot; e += TPB) {
                    int m = e >> p.nshift, ln = e & (nstrip - 1);
                    int n = n0 + ln, b = m0 + m;
                    float z = sm[e] + p.b1[n];
                    float s = 2.f * sigm(z);
                    __stcg(p.out + b * p.ostride + n,
                           s * __ldcg(p.mult + b * p.mstride + n));
                }
            } else {
                const int u0 = n0 >> 2;
                for (int e = tid; e < 1024; e += TPB) {
                    int m = e >> 4, lu = e & 15;
                    int u = u0 + lu, b = m0 + m;
                    const float* g4 = sm + m*64 + lu*4;
                    float zi = g4[0] + p.b1[u]         + p.b2[u];
                    float zf = g4[1] + p.b1[Hsz+u]     + p.b2[Hsz+u];
                    float zg = g4[2] + p.b1[2*Hsz+u]   + p.b2[2*Hsz+u];
                    float zo = g4[3] + p.b1[3*Hsz+u]   + p.b2[3*Hsz+u];
                    float cn = sigm(zf) * __ldcg(p.fc + b*Hsz + u) + sigm(zi) * tanhf(zg);
                    float hn = sigm(zo) * tanhf(cn);
                    __stcg(p.fc + b*Hsz + u, cn);
                    __stcg(p.fh + b*Hsz + u, hn);
                }
            }
        } else {
            // split-K: accumulate into g_acc, last CTA per tile runs the epilogue
            const int tot = nstrip << 6;
            for (int e = tid; e < tot; e += TPB) {
                int m = e >> p.nshift, ln = e & (nstrip - 1);
                atomicAdd(g_acc + (m0 + m) * ISZ + n0 + ln, sm[e]);
            }
            __threadfence();
            __syncthreads();
            if (tid == 0) s_last = (atomicAdd(&g_cnt[tile], 1) == p.kch - 1) ? 1 : 0;
            __syncthreads();
            if (s_last) {
                if (tid == 0) g_cnt[tile] = 0;
                for (int e = tid; e < tot; e += TPB) {
                    int m = e >> p.nshift, ln = e & (nstrip - 1);
                    int n = n0 + ln, b = m0 + m;
                    float* ap = g_acc + b * ISZ + n;
                    float z = __ldcg(ap) + p.b1[n];
                    __stcg(ap, 0.f);
                    float s = 2.f * sigm(z);
                    __stcg(p.out + b * p.ostride + n,
                           s * __ldcg(p.mult + b * p.mstride + n));
                }
            }
        }
    }
    gridbar();
}

__device__ __forceinline__ P mogP(const float* A, int K, const float* W, int KW,
                                  int N, int nshift, int kch, const float* bias,
                                  const float* mult, int mstride,
                                  float* out, int ostride) {
    P p;
    p.A1 = A; p.A2 = A; p.K1 = K; p.Ktot = K;
    p.W1 = W; p.W2 = W; p.KW1 = KW; p.lstm = 0;
    p.N = N; p.nshift = nshift; p.kch = kch;
    p.b1 = bias; p.b2 = bias;
    p.mult = mult; p.mstride = mstride;
    p.out = out; p.ostride = ostride;
    p.fc = 0; p.fh = 0;
    return p;
}

__device__ __forceinline__ P lstmP(const float* A1, int K1, const float* A2, int Ktot,
                                   const float* Wih, const float* Whh,
                                   const float* bih, const float* bhh,
                                   float* fc, float* fh) {
    P p;
    p.A1 = A1; p.A2 = A2; p.K1 = K1; p.Ktot = Ktot;
    p.W1 = Wih; p.W2 = Whh; p.KW1 = K1; p.lstm = 1;
    p.N = 4096; p.nshift = 6; p.kch = 1;
    p.b1 = bih; p.b2 = bhh;
    p.mult = 0; p.mstride = 0; p.out = 0; p.ostride = 0;
    p.fc = fc; p.fh = fh;
    return p;
}

__global__ void __launch_bounds__(TPB) mog_kernel(
    const float* in_seq,
    const float* c1Q, const float* c1Qb, const float* c1R, const float* c1Rb,
    const float* c1Wih, const float* c1Whh, const float* c1bih, const float* c1bhh,
    const float* c2Q, const float* c2Qb, const float* c2R, const float* c2Rb,
    const float* c2Wih, const float* c2Whh, const float* c2bih, const float* c2bhh,
    const float* linW, const float* linb, float* out)
{
    for (int i = blockIdx.x*TPB + threadIdx.x; i < Bsz*Hsz; i += NB*TPB) {
        g_h1[i] = 0.f; g_c1[i] = 0.f; g_h2[i] = 0.f; g_c2[i] = 0.f;
    }
    gridbar();

    for (int t = 0; t < Tsz; ++t) {
        // ---- layer 1 mogrify ----
        // x = 2s(h1 Q0^T + b) * x_t       N=128, K=1024, split-K 16, nstrip 32
        run_phase(mogP(g_h1, Hsz, c1Q,             Hsz, ISZ, 5, 16, c1Qb,
                       in_seq + t*ISZ, Tsz*ISZ, g_x, ISZ));
        // hm = 2s(x R0^T + b) * h1        N=1024, K=128, full-K, nstrip 16
        run_phase(mogP(g_x,  ISZ, c1R,             ISZ, Hsz, 4, 1, c1Rb,
                       g_h1, Hsz, g_hm, Hsz));
        // x *= 2s(hm Q1^T + b)
        run_phase(mogP(g_hm, Hsz, c1Q + ISZ*Hsz,   Hsz, ISZ, 5, 16, c1Qb + ISZ,
                       g_x, ISZ, g_x, ISZ));
        // hm *= 2s(x R1^T + b)
        run_phase(mogP(g_x,  ISZ, c1R + Hsz*ISZ,   ISZ, Hsz, 4, 1, c1Rb + Hsz,
                       g_hm, Hsz, g_hm, Hsz));
        // x *= 2s(hm Q2^T + b)
        run_phase(mogP(g_hm, Hsz, c1Q + 2*ISZ*Hsz, Hsz, ISZ, 5, 16, c1Qb + 2*ISZ,
                       g_x, ISZ, g_x, ISZ));
        // ---- layer 1 LSTM ----
        run_phase(lstmP(g_x, ISZ, g_hm, ISZ + Hsz, c1Wih, c1Whh, c1bih, c1bhh,
                        g_c1, g_h1));
        // ---- layer 2 mogrify ----
        run_phase(mogP(g_h2, Hsz, c2Q,             Hsz, Hsz, 5, 1, c2Qb,
                       g_h1, Hsz, g_x2, Hsz));
        run_phase(mogP(g_x2, Hsz, c2R,             Hsz, Hsz, 5, 1, c2Rb,
                       g_h2, Hsz, g_hm, Hsz));
        run_phase(mogP(g_hm, Hsz, c2Q + Hsz*Hsz,   Hsz, Hsz, 5, 1, c2Qb + Hsz,
                       g_x2, Hsz, g_x2, Hsz));
        run_phase(mogP(g_x2, Hsz, c2R + Hsz*Hsz,   Hsz, Hsz, 5, 1, c2Rb + Hsz,
                       g_hm, Hsz, g_hm, Hsz));
        run_phase(mogP(g_hm, Hsz, c2Q + 2*Hsz*Hsz, Hsz, Hsz, 5, 1, c2Qb + 2*Hsz,
                       g_x2, Hsz, g_x2, Hsz));
        // ---- layer 2 LSTM ----
        run_phase(lstmP(g_x2, Hsz, g_hm, 2*Hsz, c2Wih, c2Whh, c2bih, c2bhh,
                        g_c2, g_h2));
    }

    // final linear: out[b] = h2[b,:] . linW + linb
    if (blockIdx.x == 0) {
        int tid = threadIdx.x;
        int b = tid >> 1, half = tid & 1;
        const float* hrow = g_h2 + b*Hsz + half*512;
        const float* w    = linW + half*512;
        float s = 0.f;
        for (int j = 0; j < 512; ++j) s += __ldcg(hrow + j) * w[j];
        s += __shfl_xor_sync(0xffffffffu, s, 1);
        if (half == 0) out[b] = s + linb[0];
    }
}

extern "C" void kernel_launch(void* const* d_in, const int* in_sizes, int n_in,
                              void* d_out, int out_size) {
    (void)in_sizes; (void)n_in; (void)out_size;
    const float* in_seq = (const float*)d_in[0];
    const float* c1Q    = (const float*)d_in[1];
    const float* c1Qb   = (const float*)d_in[2];
    const float* c1R    = (const float*)d_in[3];
    const float* c1Rb   = (const float*)d_in[4];
    const float* c1Wih  = (const float*)d_in[5];
    const float* c1Whh  = (const float*)d_in[6];
    const float* c1bih  = (const float*)d_in[7];
    const float* c1bhh  = (const float*)d_in[8];
    const float* c2Q    = (const float*)d_in[9];
    const float* c2Qb   = (const float*)d_in[10];
    const float* c2R    = (const float*)d_in[11];
    const float* c2Rb   = (const float*)d_in[12];
    const float* c2Wih  = (const float*)d_in[13];
    const float* c2Whh  = (const float*)d_in[14];
    const float* c2bih  = (const float*)d_in[15];
    const float* c2bhh  = (const float*)d_in[16];
    const float* linW   = (const float*)d_in[17];
    const float* linb   = (const float*)d_in[18];
    mog_kernel<<<NB, TPB>>>(in_seq, c1Q, c1Qb, c1R, c1Rb, c1Wih, c1Whh, c1bih, c1bhh,
                            c2Q, c2Qb, c2R, c2Rb, c2Wih, c2Whh, c2bih, c2bhh,
                            linW, linb, (float*)d_out);
}

// round 3
// speedup vs baseline: 1.7346x; 1.6459x over previous
#include <cuda_runtime.h>
#include <mma.h>
#include <math.h>

using namespace nvcuda;

#define NB   128
#define TPB  256
#define Bsz  128
#define Tsz  512
#define ISZ  128
#define Hsz  1024
#define ACCW 4096
#define SMEM_BYTES (24576 * 4)   // A bufs 64KB + W bufs 32KB

// ---------------- persistent state --------------------------------------------
__device__ float g_h1[Bsz*Hsz];
__device__ float g_c1[Bsz*Hsz];
__device__ float g_h2[Bsz*Hsz];
__device__ float g_c2[Bsz*Hsz];
__device__ float g_x [Bsz*ISZ];
__device__ float g_x2[Bsz*Hsz];
__device__ float g_hm[Bsz*Hsz];
__device__ float g_acc[Bsz*ACCW];    // split-K accumulator (zeroed by finishers)
__device__ int   g_cnt[64];
__device__ unsigned g_barcnt;
__device__ volatile unsigned g_bargen;

// ---------------- grid barrier ------------------------------------------------
__device__ __forceinline__ void gridbar() {
    __syncthreads();
    if (threadIdx.x == 0) {
        __threadfence();
        unsigned gen = g_bargen;
        if (atomicAdd(&g_barcnt, 1u) == (unsigned)(gridDim.x - 1)) {
            g_barcnt = 0;
            __threadfence();
            atomicExch((unsigned*)&g_bargen, gen + 1u);
        } else {
            while (g_bargen == gen) { __nanosleep(32); }
        }
        __threadfence();
    }
    __syncthreads();
}

__device__ __forceinline__ float sigm(float z) { return 1.f / (1.f + expf(-z)); }
__device__ __forceinline__ float t32(float v)  { return wmma::__float_to_tf32(v); }

// ---------------- phase descriptor --------------------------------------------
struct P {
    const float *A1, *A2; int K1, Ktot;  // A(b,k): k<K1 -> A1[b*K1+k] else A2[b*Hsz+k-K1]
    const float *W1, *W2; int KW1;       // weights; lstm: n=u*4+g -> row=g*Hsz+u, split at K1
    int lstm;
    int N, kch;
    const float *b1, *b2;
    const float *mult; int mstride;      // mog epilogue multiplicand
    float *out; int ostride;             // mog output
    float *fc, *fh;                      // lstm state
};

// one GEMM phase: M=128 x NSTRIP tile per CTA, split-K across kch chunks,
// 32-k macro-tiles, register prefetch + double-buffered smem, 3xTF32 wmma.
template<int NSHIFT>
__device__ __noinline__ void run_phase(const P p) {
    constexpr int NSTRIP = 1 << NSHIFT;
    constexpr int NFR    = NSTRIP / 16;
    extern __shared__ float sm[];        // [0,16384): A bufs, [16384,24576): W bufs
    float* const Wb = sm + 16384;
    __shared__ int s_last;

    const int tid = threadIdx.x;
    const int wid = tid >> 5;
    const int ntiles = p.N >> NSHIFT;
    const int cta = blockIdx.x;

    if (cta < ntiles * p.kch) {
        const int tile = cta / p.kch, kc = cta - tile * p.kch;
        const int n0 = tile << NSHIFT;
        const int KL = p.Ktot / p.kch;   // multiple of 32 by construction
        const int k0 = kc * KL;
        const int niter = KL >> 5;

        wmma::fragment<wmma::accumulator, 16, 16, 8, float> C[NFR];
        #pragma unroll
        for (int i = 0; i < NFR; i++) wmma::fill_fragment(C[i], 0.f);

        float4 aR[4];
        float4 wR[2];

        auto loadA = [&](int kg) {
            #pragma unroll
            for (int i = 0; i < 4; i++) {
                int g = tid + (i << 8);
                int row = g >> 3, k = kg + ((g & 7) << 2);
                const float* s = (k < p.K1) ? p.A1 + row * p.K1 + k
                                            : p.A2 + row * Hsz + (k - p.K1);
                aR[i] = __ldcg((const float4*)s);
            }
        };
        auto loadW = [&](int kg) {
            #pragma unroll
            for (int i = 0; i < 2; i++) {
                int g = tid + (i << 8);
                if (g < NSTRIP * 8) {
                    int n = n0 + (g >> 3), k = kg + ((g & 7) << 2);
                    int row = p.lstm ? ((n & 3) * Hsz + (n >> 2)) : n;
                    const float* s = (k < p.K1) ? p.W1 + row * p.KW1 + k
                                                : p.W2 + row * Hsz + (k - p.K1);
                    wR[i] = *(const float4*)s;
                }
            }
        };
        auto stage = [&](int buf) {
            float* AH = sm + buf * 8192;
            float* AL = AH + 4096;
            #pragma unroll
            for (int i = 0; i < 4; i++) {
                int g = tid + (i << 8);
                int o = (g >> 3) * 32 + ((g & 7) << 2);
                float4 v = aR[i];
                float h;
                h = t32(v.x); AH[o+0] = h; AL[o+0] = t32(v.x - h);
                h = t32(v.y); AH[o+1] = h; AL[o+1] = t32(v.y - h);
                h = t32(v.z); AH[o+2] = h; AL[o+2] = t32(v.z - h);
                h = t32(v.w); AH[o+3] = h; AL[o+3] = t32(v.w - h);
            }
            float* WH = Wb + buf * 4096;
            float* WL = WH + 2048;
            #pragma unroll
            for (int i = 0; i < 2; i++) {
                int g = tid + (i << 8);
                if (g < NSTRIP * 8) {
                    int nn = g >> 3, kq = (g & 7) << 2;
                    float4 v = wR[i];
                    float h;
                    h = t32(v.x); WH[(kq+0)*NSTRIP+nn] = h; WL[(kq+0)*NSTRIP+nn] = t32(v.x - h);
                    h = t32(v.y); WH[(kq+1)*NSTRIP+nn] = h; WL[(kq+1)*NSTRIP+nn] = t32(v.y - h);
                    h = t32(v.z); WH[(kq+2)*NSTRIP+nn] = h; WL[(kq+2)*NSTRIP+nn] = t32(v.z - h);
                    h = t32(v.w); WH[(kq+3)*NSTRIP+nn] = h; WL[(kq+3)*NSTRIP+nn] = t32(v.w - h);
                }
            }
        };
        auto compute = [&](int buf) {
            const float* AH = sm + buf * 8192;
            const float* AL = AH + 4096;
            const float* WH = Wb + buf * 4096;
            const float* WL = WH + 2048;
            #pragma unroll
            for (int ks = 0; ks < 4; ++ks) {
                wmma::fragment<wmma::matrix_a, 16,16,8, wmma::precision::tf32, wmma::row_major> fAH, fAL;
                wmma::load_matrix_sync(fAH, AH + wid * 512 + ks * 8, 32);
                wmma::load_matrix_sync(fAL, AL + wid * 512 + ks * 8, 32);
                #pragma unroll
                for (int nf = 0; nf < NFR; ++nf) {
                    wmma::fragment<wmma::matrix_b, 16,16,8, wmma::precision::tf32, wmma::row_major> fBH, fBL;
                    wmma::load_matrix_sync(fBH, WH + ks * 8 * NSTRIP + nf * 16, NSTRIP);
                    wmma::load_matrix_sync(fBL, WL + ks * 8 * NSTRIP + nf * 16, NSTRIP);
                    wmma::mma_sync(C[nf], fAH, fBH, C[nf]);
                    wmma::mma_sync(C[nf], fAH, fBL, C[nf]);
                    wmma::mma_sync(C[nf], fAL, fBH, C[nf]);
                }
            }
        };

        // ---- pipelined K loop: 1 sync per macro-iter ----
        loadA(k0); loadW(k0);
        stage(0);
        __syncthreads();
        for (int it = 0; it < niter; ++it) {
            const int cur = it & 1;
            const bool more = (it + 1 < niter);
            if (more) { loadA(k0 + ((it + 1) << 5)); loadW(k0 + ((it + 1) << 5)); }
            compute(cur);
            if (more) stage(cur ^ 1);
            __syncthreads();
        }

        // ---- dump C to smem out tile (128 x NSTRIP, ld=NSTRIP) ----
        #pragma unroll
        for (int nf = 0; nf < NFR; ++nf)
            wmma::store_matrix_sync(sm + wid * 16 * NSTRIP + nf * 16, C[nf], NSTRIP,
                                    wmma::mem_row_major);
        __syncthreads();

        // ---- split-K accumulate ----
        for (int e = tid; e < 128 * NSTRIP; e += TPB) {
            int m = e >> NSHIFT, ln = e & (NSTRIP - 1);
            atomicAdd(g_acc + m * ACCW + n0 + ln, sm[e]);
        }
        __threadfence();
        __syncthreads();
        if (tid == 0) s_last = (atomicAdd(&g_cnt[tile], 1) == p.kch - 1) ? 1 : 0;
        __syncthreads();
        if (s_last) {
            if (tid == 0) g_cnt[tile] = 0;
            if (!p.lstm) {
                for (int e = tid; e < 128 * NSTRIP; e += TPB) {
                    int m = e >> NSHIFT, ln = e & (NSTRIP - 1);
                    int n = n0 + ln;
                    float* ap = g_acc + m * ACCW + n;
                    float z = __ldcg(ap) + p.b1[n];
                    __stcg(ap, 0.f);
                    float s = 2.f * sigm(z);
                    __stcg(p.out + m * p.ostride + n,
                           s * __ldcg(p.mult + m * p.mstride + n));
                }
            } else {
                constexpr int UC = NSTRIP >> 2;
                for (int e = tid; e < 128 * UC; e += TPB) {
                    int m = e >> (NSHIFT - 2), lu = e & (UC - 1);
                    int u = (n0 >> 2) + lu;
                    float* ap = g_acc + m * ACCW + n0 + lu * 4;
                    float zi = __ldcg(ap+0) + p.b1[u]         + p.b2[u];
                    float zf = __ldcg(ap+1) + p.b1[Hsz+u]     + p.b2[Hsz+u];
                    float zg = __ldcg(ap+2) + p.b1[2*Hsz+u]   + p.b2[2*Hsz+u];
                    float zo = __ldcg(ap+3) + p.b1[3*Hsz+u]   + p.b2[3*Hsz+u];
                    __stcg(ap+0, 0.f); __stcg(ap+1, 0.f);
                    __stcg(ap+2, 0.f); __stcg(ap+3, 0.f);
                    float cn = sigm(zf) * __ldcg(p.fc + m*Hsz + u) + sigm(zi) * tanhf(zg);
                    float hn = sigm(zo) * tanhf(cn);
                    __stcg(p.fc + m*Hsz + u, cn);
                    __stcg(p.fh + m*Hsz + u, hn);
                }
            }
        }
    }
    gridbar();
}

__device__ __forceinline__ P mogP(const float* A, int K, const float* W, int KW,
                                  int N, int kch, const float* bias,
                                  const float* mult, int mstride,
                                  float* out, int ostride) {
    P p;
    p.A1 = A; p.A2 = A; p.K1 = K; p.Ktot = K;
    p.W1 = W; p.W2 = W; p.KW1 = KW; p.lstm = 0;
    p.N = N; p.kch = kch;
    p.b1 = bias; p.b2 = bias;
    p.mult = mult; p.mstride = mstride;
    p.out = out; p.ostride = ostride;
    p.fc = 0; p.fh = 0;
    return p;
}

__device__ __forceinline__ P lstmP(const float* A1, int K1, const float* A2, int Ktot,
                                   const float* Wih, const float* Whh,
                                   const float* bih, const float* bhh,
                                   float* fc, float* fh, int kch) {
    P p;
    p.A1 = A1; p.A2 = A2; p.K1 = K1; p.Ktot = Ktot;
    p.W1 = Wih; p.W2 = Whh; p.KW1 = K1; p.lstm = 1;
    p.N = 4096; p.kch = kch;
    p.b1 = bih; p.b2 = bhh;
    p.mult = 0; p.mstride = 0; p.out = 0; p.ostride = 0;
    p.fc = fc; p.fh = fh;
    return p;
}

__global__ void __launch_bounds__(TPB, 1) mog_kernel(
    const float* in_seq,
    const float* c1Q, const float* c1Qb, const float* c1R, const float* c1Rb,
    const float* c1Wih, const float* c1Whh, const float* c1bih, const float* c1bhh,
    const float* c2Q, const float* c2Qb, const float* c2R, const float* c2Rb,
    const float* c2Wih, const float* c2Whh, const float* c2bih, const float* c2bhh,
    const float* linW, const float* linb, float* out)
{
    for (int i = blockIdx.x*TPB + threadIdx.x; i < Bsz*Hsz; i += NB*TPB) {
        g_h1[i] = 0.f; g_c1[i] = 0.f; g_h2[i] = 0.f; g_c2[i] = 0.f;
    }
    gridbar();

    for (int t = 0; t < Tsz; ++t) {
        // ---- layer 1 mogrify ----
        // x = 2s(h1 Q0^T + b) * x_t     N=128: 8 tiles x kch16 = 128 CTAs
        run_phase<4>(mogP(g_h1, Hsz, c1Q,             Hsz, ISZ, 16, c1Qb,
                          in_seq + t*ISZ, Tsz*ISZ, g_x, ISZ));
        // hm = 2s(x R0^T + b) * h1      N=1024: 64 tiles x kch2
        run_phase<4>(mogP(g_x,  ISZ, c1R,             ISZ, Hsz,  2, c1Rb,
                          g_h1, Hsz, g_hm, Hsz));
        run_phase<4>(mogP(g_hm, Hsz, c1Q + ISZ*Hsz,   Hsz, ISZ, 16, c1Qb + ISZ,
                          g_x, ISZ, g_x, ISZ));
        run_phase<4>(mogP(g_x,  ISZ, c1R + Hsz*ISZ,   ISZ, Hsz,  2, c1Rb + Hsz,
                          g_hm, Hsz, g_hm, Hsz));
        run_phase<4>(mogP(g_hm, Hsz, c1Q + 2*ISZ*Hsz, Hsz, ISZ, 16, c1Qb + 2*ISZ,
                          g_x, ISZ, g_x, ISZ));
        // ---- layer 1 LSTM ----       N=4096: 64 tiles x kch2 (K=1152)
        run_phase<6>(lstmP(g_x, ISZ, g_hm, ISZ + Hsz, c1Wih, c1Whh, c1bih, c1bhh,
                           g_c1, g_h1, 2));
        // ---- layer 2 mogrify ----    N=1024: 32 tiles x kch4 (K=1024)
        run_phase<5>(mogP(g_h2, Hsz, c2Q,             Hsz, Hsz, 4, c2Qb,
                          g_h1, Hsz, g_x2, Hsz));
        run_phase<5>(mogP(g_x2, Hsz, c2R,             Hsz, Hsz, 4, c2Rb,
                          g_h2, Hsz, g_hm, Hsz));
        run_phase<5>(mogP(g_hm, Hsz, c2Q + Hsz*Hsz,   Hsz, Hsz, 4, c2Qb + Hsz,
                          g_x2, Hsz, g_x2, Hsz));
        run_phase<5>(mogP(g_x2, Hsz, c2R + Hsz*Hsz,   Hsz, Hsz, 4, c2Rb + Hsz,
                          g_hm, Hsz, g_hm, Hsz));
        run_phase<5>(mogP(g_hm, Hsz, c2Q + 2*Hsz*Hsz, Hsz, Hsz, 4, c2Qb + 2*Hsz,
                          g_x2, Hsz, g_x2, Hsz));
        // ---- layer 2 LSTM ----       N=4096: 64 tiles x kch2 (K=2048)
        run_phase<6>(lstmP(g_x2, Hsz, g_hm, 2*Hsz, c2Wih, c2Whh, c2bih, c2bhh,
                           g_c2, g_h2, 2));
    }

    // final linear: out[b] = h2[b,:] . linW + linb
    if (blockIdx.x == 0) {
        int tid = threadIdx.x;
        int b = tid >> 1, half = tid & 1;
        const float* hrow = g_h2 + b*Hsz + half*512;
        const float* w    = linW + half*512;
        float s = 0.f;
        for (int j = 0; j < 512; ++j) s += __ldcg(hrow + j) * w[j];
        s += __shfl_xor_sync(0xffffffffu, s, 1);
        if (half == 0) out[b] = s + linb[0];
    }
}

extern "C" void kernel_launch(void* const* d_in, const int* in_sizes, int n_in,
                              void* d_out, int out_size) {
    (void)in_sizes; (void)n_in; (void)out_size;
    cudaFuncSetAttribute(mog_kernel, cudaFuncAttributeMaxDynamicSharedMemorySize,
                         SMEM_BYTES);
    const float* in_seq = (const float*)d_in[0];
    const float* c1Q    = (const float*)d_in[1];
    const float* c1Qb   = (const float*)d_in[2];
    const float* c1R    = (const float*)d_in[3];
    const float* c1Rb   = (const float*)d_in[4];
    const float* c1Wih  = (const float*)d_in[5];
    const float* c1Whh  = (const float*)d_in[6];
    const float* c1bih  = (const float*)d_in[7];
    const float* c1bhh  = (const float*)d_in[8];
    const float* c2Q    = (const float*)d_in[9];
    const float* c2Qb   = (const float*)d_in[10];
    const float* c2R    = (const float*)d_in[11];
    const float* c2Rb   = (const float*)d_in[12];
    const float* c2Wih  = (const float*)d_in[13];
    const float* c2Whh  = (const float*)d_in[14];
    const float* c2bih  = (const float*)d_in[15];
    const float* c2bhh  = (const float*)d_in[16];
    const float* linW   = (const float*)d_in[17];
    const float* linb   = (const float*)d_in[18];
    mog_kernel<<<NB, TPB, SMEM_BYTES>>>(in_seq, c1Q, c1Qb, c1R, c1Rb,
                                        c1Wih, c1Whh, c1bih, c1bhh,
                                        c2Q, c2Qb, c2R, c2Rb,
                                        c2Wih, c2Whh, c2bih, c2bhh,
                                        linW, linb, (float*)d_out);
}

// round 4
// speedup vs baseline: 1.7351x; 1.0003x over previous
#include <cuda_runtime.h>
#include <mma.h>
#include <math.h>

using namespace nvcuda;

#define NB   128
#define TPB  256
#define Bsz  128
#define Tsz  512
#define ISZ  128
#define Hsz  1024
#define ACCW 4096
#define SMEM_BYTES (24576 * 4)   // A bufs 64KB + W bufs 32KB

// ---------------- persistent state --------------------------------------------
__device__ float g_h1[Bsz*Hsz];
__device__ float g_c1[Bsz*Hsz];
__device__ float g_h2[Bsz*Hsz];
__device__ float g_c2[Bsz*Hsz];
__device__ float g_x [Bsz*ISZ];
__device__ float g_x2[Bsz*Hsz];
__device__ float g_hm[Bsz*Hsz];
__device__ float g_acc[Bsz*ACCW];    // split-K accumulator (zeroed by finishers)
__device__ int   g_cnt[64];
__device__ unsigned g_barcnt;
__device__ volatile unsigned g_bargen;

// ---------------- grid barrier ------------------------------------------------
__device__ __forceinline__ void gridbar() {
    __syncthreads();
    if (threadIdx.x == 0) {
        __threadfence();
        unsigned gen = g_bargen;
        if (atomicAdd(&g_barcnt, 1u) == (unsigned)(gridDim.x - 1)) {
            g_barcnt = 0;
            __threadfence();
            atomicExch((unsigned*)&g_bargen, gen + 1u);
        } else {
            while (g_bargen == gen) { __nanosleep(32); }
        }
        __threadfence();
    }
    __syncthreads();
}

__device__ __forceinline__ float sigm(float z) { return 1.f / (1.f + expf(-z)); }
__device__ __forceinline__ float t32(float v)  { return wmma::__float_to_tf32(v); }

// ---------------- phase descriptor --------------------------------------------
struct P {
    const float *A1, *A2; int K1, Ktot;  // A(b,k): k<K1 -> A1[b*K1+k] else A2[b*Hsz+k-K1]
    const float *W1, *W2; int KW1;       // weights; lstm: n=u*4+g -> row=g*Hsz+u, split at K1
    int lstm;
    int N, kch;
    const float *b1, *b2;
    const float *mult; int mstride;      // mog epilogue multiplicand
    float *out; int ostride;             // mog output
    float *fc, *fh;                      // lstm state
};

// one GEMM phase: M=128 x NSTRIP tile per CTA, split-K across kch chunks,
// 32-k macro-tiles, register prefetch + double-buffered smem, 3xTF32 wmma.
template<int NSHIFT>
__device__ __noinline__ void run_phase(const P p) {
    constexpr int NSTRIP = 1 << NSHIFT;
    constexpr int NFR    = NSTRIP / 16;
    extern __shared__ float sm[];        // [0,16384): A bufs, [16384,24576): W bufs
    float* const Wb = sm + 16384;
    __shared__ int s_last;

    const int tid = threadIdx.x;
    const int wid = tid >> 5;
    const int ntiles = p.N >> NSHIFT;
    const int cta = blockIdx.x;

    if (cta < ntiles * p.kch) {
        const int tile = cta / p.kch, kc = cta - tile * p.kch;
        const int n0 = tile << NSHIFT;
        const int KL = p.Ktot / p.kch;   // multiple of 32 by construction
        const int k0 = kc * KL;
        const int niter = KL >> 5;

        wmma::fragment<wmma::accumulator, 16, 16, 8, float> C[NFR];
        #pragma unroll
        for (int i = 0; i < NFR; i++) wmma::fill_fragment(C[i], 0.f);

        float4 aR[4];
        float4 wR[2];

        auto loadA = [&](int kg) {
            #pragma unroll
            for (int i = 0; i < 4; i++) {
                int g = tid + (i << 8);
                int row = g >> 3, k = kg + ((g & 7) << 2);
                const float* s = (k < p.K1) ? p.A1 + row * p.K1 + k
                                            : p.A2 + row * Hsz + (k - p.K1);
                aR[i] = __ldcg((const float4*)s);
            }
        };
        auto loadW = [&](int kg) {
            #pragma unroll
            for (int i = 0; i < 2; i++) {
                int g = tid + (i << 8);
                if (g < NSTRIP * 8) {
                    int n = n0 + (g >> 3), k = kg + ((g & 7) << 2);
                    int row = p.lstm ? ((n & 3) * Hsz + (n >> 2)) : n;
                    const float* s = (k < p.K1) ? p.W1 + row * p.KW1 + k
                                                : p.W2 + row * Hsz + (k - p.K1);
                    wR[i] = *(const float4*)s;
                }
            }
        };
        auto stage = [&](int buf) {
            float* AH = sm + buf * 8192;
            float* AL = AH + 4096;
            #pragma unroll
            for (int i = 0; i < 4; i++) {
                int g = tid + (i << 8);
                int o = (g >> 3) * 32 + ((g & 7) << 2);
                float4 v = aR[i];
                float h;
                h = t32(v.x); AH[o+0] = h; AL[o+0] = t32(v.x - h);
                h = t32(v.y); AH[o+1] = h; AL[o+1] = t32(v.y - h);
                h = t32(v.z); AH[o+2] = h; AL[o+2] = t32(v.z - h);
                h = t32(v.w); AH[o+3] = h; AL[o+3] = t32(v.w - h);
            }
            float* WH = Wb + buf * 4096;
            float* WL = WH + 2048;
            #pragma unroll
            for (int i = 0; i < 2; i++) {
                int g = tid + (i << 8);
                if (g < NSTRIP * 8) {
                    int nn = g >> 3, kq = (g & 7) << 2;
                    float4 v = wR[i];
                    float h;
                    h = t32(v.x); WH[(kq+0)*NSTRIP+nn] = h; WL[(kq+0)*NSTRIP+nn] = t32(v.x - h);
                    h = t32(v.y); WH[(kq+1)*NSTRIP+nn] = h; WL[(kq+1)*NSTRIP+nn] = t32(v.y - h);
                    h = t32(v.z); WH[(kq+2)*NSTRIP+nn] = h; WL[(kq+2)*NSTRIP+nn] = t32(v.z - h);
                    h = t32(v.w); WH[(kq+3)*NSTRIP+nn] = h; WL[(kq+3)*NSTRIP+nn] = t32(v.w - h);
                }
            }
        };
        auto compute = [&](int buf) {
            const float* AH = sm + buf * 8192;
            const float* AL = AH + 4096;
            const float* WH = Wb + buf * 4096;
            const float* WL = WH + 2048;
            #pragma unroll
            for (int ks = 0; ks < 4; ++ks) {
                wmma::fragment<wmma::matrix_a, 16,16,8, wmma::precision::tf32, wmma::row_major> fAH, fAL;
                wmma::load_matrix_sync(fAH, AH + wid * 512 + ks * 8, 32);
                wmma::load_matrix_sync(fAL, AL + wid * 512 + ks * 8, 32);
                #pragma unroll
                for (int nf = 0; nf < NFR; ++nf) {
                    wmma::fragment<wmma::matrix_b, 16,16,8, wmma::precision::tf32, wmma::row_major> fBH, fBL;
                    wmma::load_matrix_sync(fBH, WH + ks * 8 * NSTRIP + nf * 16, NSTRIP);
                    wmma::load_matrix_sync(fBL, WL + ks * 8 * NSTRIP + nf * 16, NSTRIP);
                    wmma::mma_sync(C[nf], fAH, fBH, C[nf]);
                    wmma::mma_sync(C[nf], fAH, fBL, C[nf]);
                    wmma::mma_sync(C[nf], fAL, fBH, C[nf]);
                }
            }
        };

        // ---- pipelined K loop: 1 sync per macro-iter ----
        loadA(k0); loadW(k0);
        stage(0);
        __syncthreads();
        for (int it = 0; it < niter; ++it) {
            const int cur = it & 1;
            const bool more = (it + 1 < niter);
            if (more) { loadA(k0 + ((it + 1) << 5)); loadW(k0 + ((it + 1) << 5)); }
            compute(cur);
            if (more) stage(cur ^ 1);
            __syncthreads();
        }

        // ---- dump C to smem out tile (128 x NSTRIP, ld=NSTRIP) ----
        #pragma unroll
        for (int nf = 0; nf < NFR; ++nf)
            wmma::store_matrix_sync(sm + wid * 16 * NSTRIP + nf * 16, C[nf], NSTRIP,
                                    wmma::mem_row_major);
        __syncthreads();

        // ---- split-K accumulate ----
        for (int e = tid; e < 128 * NSTRIP; e += TPB) {
            int m = e >> NSHIFT, ln = e & (NSTRIP - 1);
            atomicAdd(g_acc + m * ACCW + n0 + ln, sm[e]);
        }
        __threadfence();
        __syncthreads();
        if (tid == 0) s_last = (atomicAdd(&g_cnt[tile], 1) == p.kch - 1) ? 1 : 0;
        __syncthreads();
        if (s_last) {
            if (tid == 0) g_cnt[tile] = 0;
            if (!p.lstm) {
                for (int e = tid; e < 128 * NSTRIP; e += TPB) {
                    int m = e >> NSHIFT, ln = e & (NSTRIP - 1);
                    int n = n0 + ln;
                    float* ap = g_acc + m * ACCW + n;
                    float z = __ldcg(ap) + p.b1[n];
                    __stcg(ap, 0.f);
                    float s = 2.f * sigm(z);
                    __stcg(p.out + m * p.ostride + n,
                           s * __ldcg(p.mult + m * p.mstride + n));
                }
            } else {
                constexpr int UC = NSTRIP >> 2;
                for (int e = tid; e < 128 * UC; e += TPB) {
                    int m = e >> (NSHIFT - 2), lu = e & (UC - 1);
                    int u = (n0 >> 2) + lu;
                    float* ap = g_acc + m * ACCW + n0 + lu * 4;
                    float zi = __ldcg(ap+0) + p.b1[u]         + p.b2[u];
                    float zf = __ldcg(ap+1) + p.b1[Hsz+u]     + p.b2[Hsz+u];
                    float zg = __ldcg(ap+2) + p.b1[2*Hsz+u]   + p.b2[2*Hsz+u];
                    float zo = __ldcg(ap+3) + p.b1[3*Hsz+u]   + p.b2[3*Hsz+u];
                    __stcg(ap+0, 0.f); __stcg(ap+1, 0.f);
                    __stcg(ap+2, 0.f); __stcg(ap+3, 0.f);
                    float cn = sigm(zf) * __ldcg(p.fc + m*Hsz + u) + sigm(zi) * tanhf(zg);
                    float hn = sigm(zo) * tanhf(cn);
                    __stcg(p.fc + m*Hsz + u, cn);
                    __stcg(p.fh + m*Hsz + u, hn);
                }
            }
        }
    }
    gridbar();
}

__device__ __forceinline__ P mogP(const float* A, int K, const float* W, int KW,
                                  int N, int kch, const float* bias,
                                  const float* mult, int mstride,
                                  float* out, int ostride) {
    P p;
    p.A1 = A; p.A2 = A; p.K1 = K; p.Ktot = K;
    p.W1 = W; p.W2 = W; p.KW1 = KW; p.lstm = 0;
    p.N = N; p.kch = kch;
    p.b1 = bias; p.b2 = bias;
    p.mult = mult; p.mstride = mstride;
    p.out = out; p.ostride = ostride;
    p.fc = 0; p.fh = 0;
    return p;
}

__device__ __forceinline__ P lstmP(const float* A1, int K1, const float* A2, int Ktot,
                                   const float* Wih, const float* Whh,
                                   const float* bih, const float* bhh,
                                   float* fc, float* fh, int kch) {
    P p;
    p.A1 = A1; p.A2 = A2; p.K1 = K1; p.Ktot = Ktot;
    p.W1 = Wih; p.W2 = Whh; p.KW1 = K1; p.lstm = 1;
    p.N = 4096; p.kch = kch;
    p.b1 = bih; p.b2 = bhh;
    p.mult = 0; p.mstride = 0; p.out = 0; p.ostride = 0;
    p.fc = fc; p.fh = fh;
    return p;
}

__global__ void __launch_bounds__(TPB, 1) mog_kernel(
    const float* in_seq,
    const float* c1Q, const float* c1Qb, const float* c1R, const float* c1Rb,
    const float* c1Wih, const float* c1Whh, const float* c1bih, const float* c1bhh,
    const float* c2Q, const float* c2Qb, const float* c2R, const float* c2Rb,
    const float* c2Wih, const float* c2Whh, const float* c2bih, const float* c2bhh,
    const float* linW, const float* linb, float* out)
{
    for (int i = blockIdx.x*TPB + threadIdx.x; i < Bsz*Hsz; i += NB*TPB) {
        g_h1[i] = 0.f; g_c1[i] = 0.f; g_h2[i] = 0.f; g_c2[i] = 0.f;
    }
    gridbar();

    for (int t = 0; t < Tsz; ++t) {
        // ---- layer 1 mogrify ----
        // x = 2s(h1 Q0^T + b) * x_t     N=128: 8 tiles x kch16 = 128 CTAs
        run_phase<4>(mogP(g_h1, Hsz, c1Q,             Hsz, ISZ, 16, c1Qb,
                          in_seq + t*ISZ, Tsz*ISZ, g_x, ISZ));
        // hm = 2s(x R0^T + b) * h1      N=1024: 64 tiles x kch2
        run_phase<4>(mogP(g_x,  ISZ, c1R,             ISZ, Hsz,  2, c1Rb,
                          g_h1, Hsz, g_hm, Hsz));
        run_phase<4>(mogP(g_hm, Hsz, c1Q + ISZ*Hsz,   Hsz, ISZ, 16, c1Qb + ISZ,
                          g_x, ISZ, g_x, ISZ));
        run_phase<4>(mogP(g_x,  ISZ, c1R + Hsz*ISZ,   ISZ, Hsz,  2, c1Rb + Hsz,
                          g_hm, Hsz, g_hm, Hsz));
        run_phase<4>(mogP(g_hm, Hsz, c1Q + 2*ISZ*Hsz, Hsz, ISZ, 16, c1Qb + 2*ISZ,
                          g_x, ISZ, g_x, ISZ));
        // ---- layer 1 LSTM ----       N=4096: 64 tiles x kch2 (K=1152)
        run_phase<6>(lstmP(g_x, ISZ, g_hm, ISZ + Hsz, c1Wih, c1Whh, c1bih, c1bhh,
                           g_c1, g_h1, 2));
        // ---- layer 2 mogrify ----    N=1024: 32 tiles x kch4 (K=1024)
        run_phase<5>(mogP(g_h2, Hsz, c2Q,             Hsz, Hsz, 4, c2Qb,
                          g_h1, Hsz, g_x2, Hsz));
        run_phase<5>(mogP(g_x2, Hsz, c2R,             Hsz, Hsz, 4, c2Rb,
                          g_h2, Hsz, g_hm, Hsz));
        run_phase<5>(mogP(g_hm, Hsz, c2Q + Hsz*Hsz,   Hsz, Hsz, 4, c2Qb + Hsz,
                          g_x2, Hsz, g_x2, Hsz));
        run_phase<5>(mogP(g_x2, Hsz, c2R + Hsz*Hsz,   Hsz, Hsz, 4, c2Rb + Hsz,
                          g_hm, Hsz, g_hm, Hsz));
        run_phase<5>(mogP(g_hm, Hsz, c2Q + 2*Hsz*Hsz, Hsz, Hsz, 4, c2Qb + 2*Hsz,
                          g_x2, Hsz, g_x2, Hsz));
        // ---- layer 2 LSTM ----       N=4096: 64 tiles x kch2 (K=2048)
        run_phase<6>(lstmP(g_x2, Hsz, g_hm, 2*Hsz, c2Wih, c2Whh, c2bih, c2bhh,
                           g_c2, g_h2, 2));
    }

    // final linear: out[b] = h2[b,:] . linW + linb
    if (blockIdx.x == 0) {
        int tid = threadIdx.x;
        int b = tid >> 1, half = tid & 1;
        const float* hrow = g_h2 + b*Hsz + half*512;
        const float* w    = linW + half*512;
        float s = 0.f;
        for (int j = 0; j < 512; ++j) s += __ldcg(hrow + j) * w[j];
        s += __shfl_xor_sync(0xffffffffu, s, 1);
        if (half == 0) out[b] = s + linb[0];
    }
}

extern "C" void kernel_launch(void* const* d_in, const int* in_sizes, int n_in,
                              void* d_out, int out_size) {
    (void)in_sizes; (void)n_in; (void)out_size;
    cudaFuncSetAttribute(mog_kernel, cudaFuncAttributeMaxDynamicSharedMemorySize,
                         SMEM_BYTES);
    const float* in_seq = (const float*)d_in[0];
    const float* c1Q    = (const float*)d_in[1];
    const float* c1Qb   = (const float*)d_in[2];
    const float* c1R    = (const float*)d_in[3];
    const float* c1Rb   = (const float*)d_in[4];
    const float* c1Wih  = (const float*)d_in[5];
    const float* c1Whh  = (const float*)d_in[6];
    const float* c1bih  = (const float*)d_in[7];
    const float* c1bhh  = (const float*)d_in[8];
    const float* c2Q    = (const float*)d_in[9];
    const float* c2Qb   = (const float*)d_in[10];
    const float* c2R    = (const float*)d_in[11];
    const float* c2Rb   = (const float*)d_in[12];
    const float* c2Wih  = (const float*)d_in[13];
    const float* c2Whh  = (const float*)d_in[14];
    const float* c2bih  = (const float*)d_in[15];
    const float* c2bhh  = (const float*)d_in[16];
    const float* linW   = (const float*)d_in[17];
    const float* linb   = (const float*)d_in[18];
    mog_kernel<<<NB, TPB, SMEM_BYTES>>>(in_seq, c1Q, c1Qb, c1R, c1Rb,
                                        c1Wih, c1Whh, c1bih, c1bhh,
                                        c2Q, c2Qb, c2R, c2Rb,
                                        c2Wih, c2Whh, c2bih, c2bhh,
                                        linW, linb, (float*)d_out);
}

// round 6
// speedup vs baseline: 2.1925x; 1.2636x over previous
#include <cuda_runtime.h>
#include <mma.h>
#include <math.h>
#include <cstdint>

using namespace nvcuda;

#define NB   128
#define TPB  512
#define Bsz  128
#define Tsz  512
#define ISZ  128
#define Hsz  1024
#define ACCW 4096
#define SMEM_BYTES 108544   // 18432 (A bufs) + 8704 (W bufs, NSTRIP=64) floats

// ---- preconverted weight planes: [k][n] layout per phase, tf32 hi/lo ----------
#define WTOT 19005440
__device__ float g_whi[WTOT];
__device__ float g_wlo[WTOT];
// phase offsets
#define OQ1(i) ((size_t)(i)*131072)
#define OR1(i) (393216 + (size_t)(i)*131072)
#define OL1    655360
#define OQ2(i) (5373952 + (size_t)(i)*1048576)
#define OR2(i) (8519680 + (size_t)(i)*1048576)
#define OL2    10616832

// ---------------- persistent state --------------------------------------------
__device__ float g_h1[Bsz*Hsz];
__device__ float g_c1[Bsz*Hsz];
__device__ float g_h2[Bsz*Hsz];
__device__ float g_c2[Bsz*Hsz];
__device__ float g_x [Bsz*ISZ];
__device__ float g_x2[Bsz*Hsz];
__device__ float g_hm[Bsz*Hsz];
__device__ float g_acc[Bsz*ACCW];
__device__ int   g_cnt[64];
__device__ unsigned g_barcnt;
__device__ volatile unsigned g_bargen;

__device__ __forceinline__ float sigm(float z) { return 1.f / (1.f + expf(-z)); }
__device__ __forceinline__ float t32(float v)  { return wmma::__float_to_tf32(v); }

__device__ __forceinline__ void cpa16(unsigned int dst, const void* src) {
    asm volatile("cp.async.cg.shared.global [%0], [%1], 16;\n" :: "r"(dst), "l"(src));
}
__device__ __forceinline__ void cpa_commit() { asm volatile("cp.async.commit_group;\n"); }
__device__ __forceinline__ void cpa_waitall() { asm volatile("cp.async.wait_all;\n"); }

// ---------------- grid barrier ------------------------------------------------
__device__ __forceinline__ void gridbar() {
    __syncthreads();
    if (threadIdx.x == 0) {
        __threadfence();
        unsigned gen = g_bargen;
        if (atomicAdd(&g_barcnt, 1u) == (unsigned)(gridDim.x - 1)) {
            g_barcnt = 0;
            __threadfence();
            atomicExch((unsigned*)&g_bargen, gen + 1u);
        } else {
            while (g_bargen == gen) { __nanosleep(32); }
        }
        __threadfence();
    }
    __syncthreads();
}

// ---------------- weight preconversion (once per launch) ----------------------
__global__ void preconv_kernel(
    const float* c1Q, const float* c1R, const float* c1Wih, const float* c1Whh,
    const float* c2Q, const float* c2R, const float* c2Wih, const float* c2Whh)
{
    int seg = blockIdx.y;
    const float *src = 0, *src2 = 0;
    int K = 0, N = 0, LD = 0, K1 = 0, lstm = 0;
    size_t dst = 0;
    switch (seg) {
        case 0: case 1: case 2:
            src = c1Q + (size_t)seg*131072; K = 1024; N = 128; LD = 1024; dst = OQ1(seg); break;
        case 3: case 4:
            src = c1R + (size_t)(seg-3)*131072; K = 128; N = 1024; LD = 128; dst = OR1(seg-3); break;
        case 5:
            src = c1Wih; src2 = c1Whh; K = 1152; N = 4096; K1 = 128; lstm = 1; dst = OL1; break;
        case 6: case 7: case 8:
            src = c2Q + (size_t)(seg-6)*1048576; K = 1024; N = 1024; LD = 1024; dst = OQ2(seg-6); break;
        case 9: case 10:
            src = c2R + (size_t)(seg-9)*1048576; K = 1024; N = 1024; LD = 1024; dst = OR2(seg-9); break;
        default:
            src = c2Wih; src2 = c2Whh; K = 2048; N = 4096; K1 = 1024; lstm = 1; dst = OL2; break;
    }
    size_t tot = (size_t)K * N;
    for (size_t i = (size_t)blockIdx.x*blockDim.x + threadIdx.x; i < tot;
         i += (size_t)gridDim.x*blockDim.x) {
        int k = (int)(i / N), n = (int)(i % N);
        float v;
        if (!lstm) {
            v = src[(size_t)n*LD + k];
        } else {
            int g = n & 3, u = n >> 2;
            int row = g*Hsz + u;
            v = (k < K1) ? src[(size_t)row*K1 + k] : src2[(size_t)row*Hsz + (k - K1)];
        }
        float h = t32(v);
        g_whi[dst + i] = h;
        g_wlo[dst + i] = t32(v - h);
    }
}

// ---------------- phase descriptor --------------------------------------------
struct P {
    const float *A1, *A2; int K1, Ktot;  // A(b,k): k<K1 -> A1[b*K1+k] else A2[b*Hsz+k-K1]
    size_t woff;                          // offset into g_whi/g_wlo ([k][N] layout)
    int N, kch, lstm;
    const float *b1, *b2;
    const float *mult; int mstride;
    float *out; int ostride;
    float *fc, *fh;
};

// one GEMM phase: M=128 x NSTRIP per CTA, split-K, 32-k macro-tiles,
// cp.async weights (pre-split tf32 hi/lo), register-prefetched A, 3xTF32 wmma.
template<int NSHIFT>
__device__ __noinline__ void run_phase(const P p) {
    constexpr int NSTRIP = 1 << NSHIFT;
    constexpr int WPAD   = NSTRIP + 4;
    constexpr int NW     = (NSHIFT == 6) ? 4 : 2;   // n-warps
    constexpr int MW     = 16 / NW;                 // m-warps
    constexpr int MFR    = 8 / MW;                  // 16-row frags per warp
    constexpr int WBUF   = 2 * 32 * WPAD;           // floats per W buffer (hi+lo)
    extern __shared__ float sm[];
    float* const Wb = sm + 18432;
    __shared__ int s_last;

    const int tid = threadIdx.x;
    const int wid = tid >> 5;
    const int ntiles = p.N >> NSHIFT;
    const int cta = blockIdx.x;

    if (cta < ntiles * p.kch) {
        const int tile = cta / p.kch, kc = cta - tile * p.kch;
        const int n0 = tile << NSHIFT;
        const int KL = p.Ktot / p.kch;
        const int k0 = kc * KL;
        const int niter = KL >> 5;
        const int wm = wid % MW, wn = wid / MW;

        wmma::fragment<wmma::accumulator, 16, 16, 8, float> C[MFR];
        #pragma unroll
        for (int i = 0; i < MFR; i++) wmma::fill_fragment(C[i], 0.f);

        float4 aR[2];
        const float* WHg = g_whi + p.woff;
        const float* WLg = g_wlo + p.woff;
        const unsigned int wsm = (unsigned int)__cvta_generic_to_shared(Wb);

        auto issueW = [&](int buf, int kg) {
            constexpr int NC4 = NSTRIP / 4;
            constexpr int CPL = 32 * NC4;           // 16B chunks per plane
            if (tid < CPL) {
                int kk = tid / NC4, nc = (tid - kk * NC4) << 2;
                size_t s = (size_t)(kg + kk) * p.N + (n0 + nc);
                unsigned int d = wsm + (unsigned int)(buf * WBUF + kk * WPAD + nc) * 4u;
                cpa16(d, WHg + s);
                cpa16(d + 32u * WPAD * 4u, WLg + s);
            }
            cpa_commit();
        };
        auto loadA = [&](int kg) {
            #pragma unroll
            for (int i = 0; i < 2; i++) {
                int c = tid + (i << 9);
                int row = c >> 3, kq = (c & 7) << 2;
                int k = kg + kq;
                const float* s = (k < p.K1) ? p.A1 + (size_t)row * p.K1 + k
                                            : p.A2 + (size_t)row * Hsz + (k - p.K1);
                aR[i] = __ldcg((const float4*)s);
            }
        };
        auto stageA = [&](int buf) {
            float* AH = sm + buf * 9216;
            float* AL = AH + 4608;
            #pragma unroll
            for (int i = 0; i < 2; i++) {
                int c = tid + (i << 9);
                int o = (c >> 3) * 36 + ((c & 7) << 2);
                float4 v = aR[i]; float h;
                h = t32(v.x); AH[o+0] = h; AL[o+0] = t32(v.x - h);
                h = t32(v.y); AH[o+1] = h; AL[o+1] = t32(v.y - h);
                h = t32(v.z); AH[o+2] = h; AL[o+2] = t32(v.z - h);
                h = t32(v.w); AH[o+3] = h; AL[o+3] = t32(v.w - h);
            }
        };
        auto compute = [&](int buf) {
            const float* AH = sm + buf * 9216;
            const float* AL = AH + 4608;
            const float* WH = Wb + buf * WBUF;
            const float* WL = WH + 32 * WPAD;
            #pragma unroll
            for (int ks = 0; ks < 4; ++ks) {
                wmma::fragment<wmma::matrix_b, 16,16,8, wmma::precision::tf32, wmma::row_major> bH, bL;
                wmma::load_matrix_sync(bH, WH + ks * 8 * WPAD + wn * 16, WPAD);
                wmma::load_matrix_sync(bL, WL + ks * 8 * WPAD + wn * 16, WPAD);
                #pragma unroll
                for (int mf = 0; mf < MFR; ++mf) {
                    int mrow = (wm * MFR + mf) * 16;
                    wmma::fragment<wmma::matrix_a, 16,16,8, wmma::precision::tf32, wmma::row_major> aH, aL;
                    wmma::load_matrix_sync(aH, AH + mrow * 36 + ks * 8, 36);
                    wmma::load_matrix_sync(aL, AL + mrow * 36 + ks * 8, 36);
                    wmma::mma_sync(C[mf], aH, bH, C[mf]);
                    wmma::mma_sync(C[mf], aH, bL, C[mf]);
                    wmma::mma_sync(C[mf], aL, bH, C[mf]);
                }
            }
        };

        // ---- pipelined K loop ----
        issueW(0, k0);
        loadA(k0);
        stageA(0);
        cpa_waitall();
        __syncthreads();
        for (int it = 0; it < niter; ++it) {
            const int cur = it & 1;
            const bool more = (it + 1 < niter);
            if (more) { issueW(cur ^ 1, k0 + ((it + 1) << 5)); loadA(k0 + ((it + 1) << 5)); }
            compute(cur);
            if (more) stageA(cur ^ 1);
            cpa_waitall();
            __syncthreads();
        }

        // ---- dump C to smem out tile (128 x NSTRIP, ld=NSTRIP) ----
        #pragma unroll
        for (int mf = 0; mf < MFR; ++mf)
            wmma::store_matrix_sync(sm + ((wm * MFR + mf) * 16) * NSTRIP + wn * 16,
                                    C[mf], NSTRIP, wmma::mem_row_major);
        __syncthreads();

        // ---- split-K accumulate + fused epilogue on last CTA of tile ----
        for (int e = tid; e < 128 * NSTRIP; e += TPB) {
            int m = e >> NSHIFT, ln = e & (NSTRIP - 1);
            atomicAdd(g_acc + m * ACCW + n0 + ln, sm[e]);
        }
        __threadfence();
        __syncthreads();
        if (tid == 0) s_last = (atomicAdd(&g_cnt[tile], 1) == p.kch - 1) ? 1 : 0;
        __syncthreads();
        if (s_last) {
            if (tid == 0) g_cnt[tile] = 0;
            if (!p.lstm) {
                for (int e = tid; e < 128 * NSTRIP; e += TPB) {
                    int m = e >> NSHIFT, ln = e & (NSTRIP - 1);
                    int n = n0 + ln;
                    float* ap = g_acc + m * ACCW + n;
                    float z = __ldcg(ap) + p.b1[n];
                    __stcg(ap, 0.f);
                    float s = 2.f * sigm(z);
                    __stcg(p.out + m * p.ostride + n,
                           s * __ldcg(p.mult + m * p.mstride + n));
                }
            } else {
                constexpr int UC = NSTRIP >> 2;
                for (int e = tid; e < 128 * UC; e += TPB) {
                    int m = e >> (NSHIFT - 2), lu = e & (UC - 1);
                    int u = (n0 >> 2) + lu;
                    float* ap = g_acc + m * ACCW + n0 + lu * 4;
                    float zi = __ldcg(ap+0) + p.b1[u]         + p.b2[u];
                    float zf = __ldcg(ap+1) + p.b1[Hsz+u]     + p.b2[Hsz+u];
                    float zg = __ldcg(ap+2) + p.b1[2*Hsz+u]   + p.b2[2*Hsz+u];
                    float zo = __ldcg(ap+3) + p.b1[3*Hsz+u]   + p.b2[3*Hsz+u];
                    __stcg(ap+0, 0.f); __stcg(ap+1, 0.f);
                    __stcg(ap+2, 0.f); __stcg(ap+3, 0.f);
                    float cn = sigm(zf) * __ldcg(p.fc + m*Hsz + u) + sigm(zi) * tanhf(zg);
                    float hn = sigm(zo) * tanhf(cn);
                    __stcg(p.fc + m*Hsz + u, cn);
                    __stcg(p.fh + m*Hsz + u, hn);
                }
            }
        }
    }
    gridbar();
}

__device__ __forceinline__ P mogP(const float* A, int K, size_t woff,
                                  int N, int kch, const float* bias,
                                  const float* mult, int mstride,
                                  float* out, int ostride) {
    P p;
    p.A1 = A; p.A2 = A; p.K1 = K; p.Ktot = K;
    p.woff = woff; p.N = N; p.kch = kch; p.lstm = 0;
    p.b1 = bias; p.b2 = bias;
    p.mult = mult; p.mstride = mstride;
    p.out = out; p.ostride = ostride;
    p.fc = 0; p.fh = 0;
    return p;
}

__device__ __forceinline__ P lstmP(const float* A1, int K1, const float* A2, int Ktot,
                                   size_t woff, const float* bih, const float* bhh,
                                   float* fc, float* fh, int kch) {
    P p;
    p.A1 = A1; p.A2 = A2; p.K1 = K1; p.Ktot = Ktot;
    p.woff = woff; p.N = 4096; p.kch = kch; p.lstm = 1;
    p.b1 = bih; p.b2 = bhh;
    p.mult = 0; p.mstride = 0; p.out = 0; p.ostride = 0;
    p.fc = fc; p.fh = fh;
    return p;
}

__global__ void __launch_bounds__(TPB, 1) mog_kernel(
    const float* in_seq,
    const float* c1Qb, const float* c1Rb, const float* c1bih, const float* c1bhh,
    const float* c2Qb, const float* c2Rb, const float* c2bih, const float* c2bhh,
    const float* linW, const float* linb, float* out)
{
    for (int i = blockIdx.x*TPB + threadIdx.x; i < Bsz*Hsz; i += NB*TPB) {
        g_h1[i] = 0.f; g_c1[i] = 0.f; g_h2[i] = 0.f; g_c2[i] = 0.f;
    }
    gridbar();

    for (int t = 0; t < Tsz; ++t) {
        // ---- layer 1 mogrify ----
        run_phase<5>(mogP(g_h1, Hsz, OQ1(0), ISZ, 32, c1Qb,
                          in_seq + t*ISZ, Tsz*ISZ, g_x, ISZ));
        run_phase<5>(mogP(g_x,  ISZ, OR1(0), Hsz,  4, c1Rb,
                          g_h1, Hsz, g_hm, Hsz));
        run_phase<5>(mogP(g_hm, Hsz, OQ1(1), ISZ, 32, c1Qb + ISZ,
                          g_x, ISZ, g_x, ISZ));
        run_phase<5>(mogP(g_x,  ISZ, OR1(1), Hsz,  4, c1Rb + Hsz,
                          g_hm, Hsz, g_hm, Hsz));
        run_phase<5>(mogP(g_hm, Hsz, OQ1(2), ISZ, 32, c1Qb + 2*ISZ,
                          g_x, ISZ, g_x, ISZ));
        // ---- layer 1 LSTM ----
        run_phase<6>(lstmP(g_x, ISZ, g_hm, ISZ + Hsz, OL1, c1bih, c1bhh,
                           g_c1, g_h1, 2));
        // ---- layer 2 mogrify ----
        run_phase<6>(mogP(g_h2, Hsz, OQ2(0), Hsz, 8, c2Qb,
                          g_h1, Hsz, g_x2, Hsz));
        run_phase<6>(mogP(g_x2, Hsz, OR2(0), Hsz, 8, c2Rb,
                          g_h2, Hsz, g_hm, Hsz));
        run_phase<6>(mogP(g_hm, Hsz, OQ2(1), Hsz, 8, c2Qb + Hsz,
                          g_x2, Hsz, g_x2, Hsz));
        run_phase<6>(mogP(g_x2, Hsz, OR2(1), Hsz, 8, c2Rb + Hsz,
                          g_hm, Hsz, g_hm, Hsz));
        run_phase<6>(mogP(g_hm, Hsz, OQ2(2), Hsz, 8, c2Qb + 2*Hsz,
                          g_x2, Hsz, g_x2, Hsz));
        // ---- layer 2 LSTM ----
        run_phase<6>(lstmP(g_x2, Hsz, g_hm, 2*Hsz, OL2, c2bih, c2bhh,
                           g_c2, g_h2, 2));
    }

    // final linear
    if (blockIdx.x == 0 && threadIdx.x < 256) {
        int tid = threadIdx.x;
        int b = tid >> 1, half = tid & 1;
        const float* hrow = g_h2 + b*Hsz + half*512;
        const float* w    = linW + half*512;
        float s = 0.f;
        for (int j = 0; j < 512; ++j) s += __ldcg(hrow + j) * w[j];
        s += __shfl_xor_sync(0xffffffffu, s, 1);
        if (half == 0) out[b] = s + linb[0];
    }
}

extern "C" void kernel_launch(void* const* d_in, const int* in_sizes, int n_in,
                              void* d_out, int out_size) {
    (void)in_sizes; (void)n_in; (void)out_size;
    cudaFuncSetAttribute(mog_kernel, cudaFuncAttributeMaxDynamicSharedMemorySize,
                         SMEM_BYTES);
    const float* in_seq = (const float*)d_in[0];
    const float* c1Q    = (const float*)d_in[1];
    const float* c1Qb   = (const float*)d_in[2];
    const float* c1R    = (const float*)d_in[3];
    const float* c1Rb   = (const float*)d_in[4];
    const float* c1Wih  = (const float*)d_in[5];
    const float* c1Whh  = (const float*)d_in[6];
    const float* c1bih  = (const float*)d_in[7];
    const float* c1bhh  = (const float*)d_in[8];
    const float* c2Q    = (const float*)d_in[9];
    const float* c2Qb   = (const float*)d_in[10];
    const float* c2R    = (const float*)d_in[11];
    const float* c2Rb   = (const float*)d_in[12];
    const float* c2Wih  = (const float*)d_in[13];
    const float* c2Whh  = (const float*)d_in[14];
    const float* c2bih  = (const float*)d_in[15];
    const float* c2bhh  = (const float*)d_in[16];
    const float* linW   = (const float*)d_in[17];
    const float* linb   = (const float*)d_in[18];

    preconv_kernel<<<dim3(256, 12), 256>>>(c1Q, c1R, c1Wih, c1Whh,
                                           c2Q, c2R, c2Wih, c2Whh);
    mog_kernel<<<NB, TPB, SMEM_BYTES>>>(in_seq,
                                        c1Qb, c1Rb, c1bih, c1bhh,
                                        c2Qb, c2Rb, c2bih, c2bhh,
                                        linW, linb, (float*)d_out);
}